// round 1
// baseline (speedup 1.0000x reference)
#include <cuda_runtime.h>
#include <cstdint>

// Problem constants: x is [64,3,224,224] f32, out is [16,64,3,224,224] f32.
#define NELEM    9633792      // 64*3*224*224
#define HWPLANE  50176        // 224*224
#define TSTEPS   16
#define EPT      4            // elements per thread (float4 granularity)

struct KeyParams {
    unsigned int k0[TSTEPS];
    unsigned int k1[TSTEPS];
    unsigned int k2[TSTEPS];  // k0 ^ k1 ^ 0x1BD11BDA, precomputed on host
};

// ---------------------------------------------------------------------------
// threefry2x32 (JAX-exact: 20 rounds, 5 groups of 4, alternating rotation sets)
// ---------------------------------------------------------------------------
__device__ __forceinline__ void tf2x32_dev(unsigned k0, unsigned k1, unsigned k2,
                                           unsigned c0, unsigned c1,
                                           unsigned &o0, unsigned &o1) {
    unsigned x0 = c0 + k0;
    unsigned x1 = c1 + k1;
#define TFR(r) { x0 += x1; x1 = __funnelshift_l(x1, x1, (r)); x1 ^= x0; }
    TFR(13) TFR(15) TFR(26) TFR(6)
    x0 += k1; x1 += k2 + 1u;
    TFR(17) TFR(29) TFR(16) TFR(24)
    x0 += k2; x1 += k0 + 2u;
    TFR(13) TFR(15) TFR(26) TFR(6)
    x0 += k0; x1 += k1 + 3u;
    TFR(17) TFR(29) TFR(16) TFR(24)
    x0 += k1; x1 += k2 + 4u;
    TFR(13) TFR(15) TFR(26) TFR(6)
    x0 += k2; x1 += k0 + 5u;
#undef TFR
    o0 = x0; o1 = x1;
}

static inline unsigned rotl_host(unsigned v, int r) {
    return (v << r) | (v >> (32 - r));
}

static void tf2x32_host(unsigned k0, unsigned k1,
                        unsigned c0, unsigned c1,
                        unsigned &o0, unsigned &o1) {
    unsigned k2 = k0 ^ k1 ^ 0x1BD11BDAu;
    unsigned x0 = c0 + k0;
    unsigned x1 = c1 + k1;
#define TFRH(r) { x0 += x1; x1 = rotl_host(x1, (r)); x1 ^= x0; }
    TFRH(13) TFRH(15) TFRH(26) TFRH(6)
    x0 += k1; x1 += k2 + 1u;
    TFRH(17) TFRH(29) TFRH(16) TFRH(24)
    x0 += k2; x1 += k0 + 2u;
    TFRH(13) TFRH(15) TFRH(26) TFRH(6)
    x0 += k0; x1 += k1 + 3u;
    TFRH(17) TFRH(29) TFRH(16) TFRH(24)
    x0 += k1; x1 += k2 + 4u;
    TFRH(13) TFRH(15) TFRH(26) TFRH(6)
    x0 += k2; x1 += k0 + 5u;
#undef TFRH
    o0 = x0; o1 = x1;
}

// ---------------------------------------------------------------------------
// Main kernel: each thread owns 4 consecutive elements (same channel, since
// channel-plane boundaries are multiples of 4) across all 16 time steps.
// ---------------------------------------------------------------------------
__global__ void __launch_bounds__(256)
hyper_kernel(const float* __restrict__ x,
             const float* __restrict__ meanv,
             const float* __restrict__ stdv,
             float* __restrict__ out,
             KeyParams kp)
{
    const unsigned tid = blockIdx.x * blockDim.x + threadIdx.x;
    const unsigned j = tid * EPT;
    if (j >= NELEM) return;

    const unsigned c = (j / HWPLANE) % 3u;
    const float m = meanv[c];
    const float s = stdv[c];
    // Output values for spike=0 and spike=1: (spike - m) / s, IEEE divide.
    const float ov0 = __fdiv_rn(0.0f - m, s);
    const float ov1 = __fdiv_rn(1.0f - m, s);

    const float4 xv = *reinterpret_cast<const float4*>(x + j);

    // probs = clip(x*s + m, 0, 1)  (separate rn mul + rn add, matching XLA)
    // rem0 = probs * 16 (exact)
    float rem[EPT];
    {
        const float xs[EPT] = {xv.x, xv.y, xv.z, xv.w};
#pragma unroll
        for (int e = 0; e < EPT; e++) {
            float pr = __fadd_rn(__fmul_rn(xs[e], s), m);
            pr = fminf(fmaxf(pr, 0.0f), 1.0f);
            rem[e] = __fmul_rn(pr, 16.0f);
        }
    }

#pragma unroll 1
    for (int t = 0; t < TSTEPS; t++) {
        const float slots   = (float)(TSTEPS - t);
        const float slotsm1 = slots - 1.0f;
        const unsigned k0 = kp.k0[t];
        const unsigned k1 = kp.k1[t];
        const unsigned k2 = kp.k2[t];

        float ovals[EPT];
#pragma unroll
        for (int e = 0; e < EPT; e++) {
            // partitionable threefry: counter = (0, flat_index); bits = o0 ^ o1
            unsigned b0, b1;
            tf2x32_dev(k0, k1, k2, 0u, j + (unsigned)e, b0, b1);
            const unsigned bits = b0 ^ b1;

            // u = bitcast((bits>>9) | 0x3f800000) - 1.0  (exact subtraction)
            const float u = __uint_as_float((bits >> 9) | 0x3f800000u) - 1.0f;

            // p = clip(rem / slots, 0, 1), IEEE divide to match XLA
            float p = __fdiv_rn(rem[e], slots);
            p = fminf(fmaxf(p, 0.0f), 1.0f);

            const bool sp = (u < p);
            // rem = clip(rem - spike, 0, slots-1)  (all exact ops)
            float r2 = sp ? (rem[e] - 1.0f) : rem[e];
            rem[e] = fminf(fmaxf(r2, 0.0f), slotsm1);
            ovals[e] = sp ? ov1 : ov0;
        }

        float4 o;
        o.x = ovals[0]; o.y = ovals[1]; o.z = ovals[2]; o.w = ovals[3];
        *reinterpret_cast<float4*>(out + (size_t)t * NELEM + j) = o;
    }
}

// ---------------------------------------------------------------------------
// Launch: compute the 16 step-keys on the host (keys[t] = threefry((0,1),(0,t))
// under the partitionable/"foldlike" split) and pass them as kernel params.
// Pure CPU arithmetic + one kernel launch => graph-capturable, allocation-free.
// ---------------------------------------------------------------------------
extern "C" void kernel_launch(void* const* d_in, const int* in_sizes, int n_in,
                              void* d_out, int out_size) {
    (void)in_sizes; (void)n_in; (void)out_size;

    KeyParams kp;
    for (int t = 0; t < TSTEPS; t++) {
        unsigned o0, o1;
        // jax.random.key(1) -> key data (0, 1); split counters (hi=0, lo=t)
        tf2x32_host(0u, 1u, 0u, (unsigned)t, o0, o1);
        kp.k0[t] = o0;
        kp.k1[t] = o1;
        kp.k2[t] = o0 ^ o1 ^ 0x1BD11BDAu;
    }

    const float* x  = (const float*)d_in[0];
    const float* mn = (const float*)d_in[1];
    const float* sd = (const float*)d_in[2];
    float* out = (float*)d_out;

    const int threads = 256;
    const int blocks = (NELEM / EPT + threads - 1) / threads;  // 9408 exactly
    hyper_kernel<<<blocks, threads>>>(x, mn, sd, out, kp);
}

// round 2
// speedup vs baseline: 1.3151x; 1.3151x over previous
#include <cuda_runtime.h>
#include <cstdint>

// Problem constants: x is [64,3,224,224] f32, out is [16,64,3,224,224] f32.
#define NELEM    9633792      // 64*3*224*224
#define HWPLANE  50176        // 224*224
#define TSTEPS   16
#define EPT      4            // elements per thread (float4 granularity)

// Host-precomputed per-step constants:
//  - threefry key schedule with round constants folded in
//  - inv[t] = rn(1 / slots_t) for Markstein correctly-rounded division
struct StepParams {
    unsigned int kA0[TSTEPS], kB0[TSTEPS];             // initial inject (k0, k1)
    unsigned int kA1[TSTEPS], kB1[TSTEPS];             // (k1, k2+1)
    unsigned int kA2[TSTEPS], kB2[TSTEPS];             // (k2, k0+2)
    unsigned int kA3[TSTEPS], kB3[TSTEPS];             // (k0, k1+3)
    unsigned int kA4[TSTEPS], kB4[TSTEPS];             // (k1, k2+4)
    unsigned int kA5[TSTEPS], kB5[TSTEPS];             // (k2, k0+5)
    float        inv[TSTEPS];                          // rn(1/slots)
};

// ---------------------------------------------------------------------------
// threefry2x32 core with pre-folded key schedule (20 rounds, JAX-exact)
// ---------------------------------------------------------------------------
__device__ __forceinline__ unsigned tf2x32_bits(
    unsigned a0, unsigned b0, unsigned a1, unsigned b1,
    unsigned a2, unsigned b2, unsigned a3, unsigned b3,
    unsigned a4, unsigned b4, unsigned a5, unsigned b5,
    unsigned c1)
{
    unsigned x0 = a0;            // c0 = 0, so x0 = 0 + k0
    unsigned x1 = c1 + b0;
#define TFR(r) { x0 += x1; x1 = __funnelshift_l(x1, x1, (r)); x1 ^= x0; }
    TFR(13) TFR(15) TFR(26) TFR(6)
    x0 += a1; x1 += b1;
    TFR(17) TFR(29) TFR(16) TFR(24)
    x0 += a2; x1 += b2;
    TFR(13) TFR(15) TFR(26) TFR(6)
    x0 += a3; x1 += b3;
    TFR(17) TFR(29) TFR(16) TFR(24)
    x0 += a4; x1 += b4;
    TFR(13) TFR(15) TFR(26) TFR(6)
    x0 += a5; x1 += b5;
#undef TFR
    return x0 ^ x1;              // partitionable fold: o0 ^ o1
}

// Correctly-rounded a/b for invariant b with c = rn(1/b) (Markstein).
// For power-of-two b the residual is 0 and this is trivially exact.
__device__ __forceinline__ float div_rn_inv(float a, float b, float c) {
    float q0 = __fmul_rn(a, c);
    float r  = __fmaf_rn(-b, q0, a);
    return __fmaf_rn(r, c, q0);
}

static inline unsigned rotl_host(unsigned v, int r) {
    return (v << r) | (v >> (32 - r));
}

static void tf2x32_host(unsigned k0, unsigned k1,
                        unsigned c0, unsigned c1,
                        unsigned &o0, unsigned &o1) {
    unsigned k2 = k0 ^ k1 ^ 0x1BD11BDAu;
    unsigned x0 = c0 + k0;
    unsigned x1 = c1 + k1;
#define TFRH(r) { x0 += x1; x1 = rotl_host(x1, (r)); x1 ^= x0; }
    TFRH(13) TFRH(15) TFRH(26) TFRH(6)
    x0 += k1; x1 += k2 + 1u;
    TFRH(17) TFRH(29) TFRH(16) TFRH(24)
    x0 += k2; x1 += k0 + 2u;
    TFRH(13) TFRH(15) TFRH(26) TFRH(6)
    x0 += k0; x1 += k1 + 3u;
    TFRH(17) TFRH(29) TFRH(16) TFRH(24)
    x0 += k1; x1 += k2 + 4u;
    TFRH(13) TFRH(15) TFRH(26) TFRH(6)
    x0 += k2; x1 += k0 + 5u;
#undef TFRH
    o0 = x0; o1 = x1;
}

// ---------------------------------------------------------------------------
// Main kernel: each thread owns 4 consecutive elements (same channel) across
// all 16 time steps.
// ---------------------------------------------------------------------------
__global__ void __launch_bounds__(256)
hyper_kernel(const float* __restrict__ x,
             const float* __restrict__ meanv,
             const float* __restrict__ stdv,
             float* __restrict__ out,
             const StepParams sp)
{
    const unsigned tid = blockIdx.x * blockDim.x + threadIdx.x;
    const unsigned j = tid * EPT;
    if (j >= NELEM) return;

    const unsigned c = (j / HWPLANE) % 3u;
    const float m = meanv[c];
    const float s = stdv[c];
    // Output values for spike=0 and spike=1: (spike - m) / s, IEEE divide.
    const float ov0 = __fdiv_rn(0.0f - m, s);
    const float ov1 = __fdiv_rn(1.0f - m, s);

    const float4 xv = *reinterpret_cast<const float4*>(x + j);

    // probs = clip(x*s + m, 0, 1) (separate rn mul + rn add, matching XLA);
    // rem0 = probs * 16 (exact).
    float rem[EPT];
    {
        const float xs[EPT] = {xv.x, xv.y, xv.z, xv.w};
#pragma unroll
        for (int e = 0; e < EPT; e++) {
            float pr = __fadd_rn(__fmul_rn(xs[e], s), m);
            pr = fminf(fmaxf(pr, 0.0f), 1.0f);
            rem[e] = __fmul_rn(pr, 16.0f);
        }
    }

#pragma unroll 1
    for (int t = 0; t < TSTEPS; t++) {
        const float slots   = (float)(TSTEPS - t);
        const float slotsm1 = slots - 1.0f;
        const float invs    = sp.inv[t];
        const unsigned a0 = sp.kA0[t], b0 = sp.kB0[t];
        const unsigned a1 = sp.kA1[t], b1 = sp.kB1[t];
        const unsigned a2 = sp.kA2[t], b2 = sp.kB2[t];
        const unsigned a3 = sp.kA3[t], b3 = sp.kB3[t];
        const unsigned a4 = sp.kA4[t], b4 = sp.kB4[t];
        const unsigned a5 = sp.kA5[t], b5 = sp.kB5[t];

        float ovals[EPT];
#pragma unroll
        for (int e = 0; e < EPT; e++) {
            const unsigned bits = tf2x32_bits(a0, b0, a1, b1, a2, b2,
                                              a3, b3, a4, b4, a5, b5,
                                              j + (unsigned)e);

            // u = bitcast((bits>>9) | 0x3f800000) - 1.0 (exact subtraction)
            const float u = __uint_as_float((bits >> 9) | 0x3f800000u) - 1.0f;

            // p = rn(rem/slots); the reference's clip(p,0,1) is a provable
            // no-op because rem in [0, slots] is an invariant.
            const float p = div_rn_inv(rem[e], slots, invs);

            const bool spike = (u < p);
            const float spikef = spike ? 1.0f : 0.0f;
            // rem = clip(rem - spike, 0, slots-1) (all exact ops)
            rem[e] = fminf(fmaxf(rem[e] - spikef, 0.0f), slotsm1);
            ovals[e] = spike ? ov1 : ov0;
        }

        float4 o;
        o.x = ovals[0]; o.y = ovals[1]; o.z = ovals[2]; o.w = ovals[3];
        *reinterpret_cast<float4*>(out + (size_t)t * NELEM + j) = o;
    }
}

// ---------------------------------------------------------------------------
// Launch: compute per-step keys + folded schedule + reciprocals on the host
// (keys[t] = threefry((0,1),(0,t)) under the partitionable split).
// Pure CPU arithmetic + one kernel launch => graph-capturable, allocation-free.
// ---------------------------------------------------------------------------
extern "C" void kernel_launch(void* const* d_in, const int* in_sizes, int n_in,
                              void* d_out, int out_size) {
    (void)in_sizes; (void)n_in; (void)out_size;

    StepParams sp;
    for (int t = 0; t < TSTEPS; t++) {
        unsigned k0, k1;
        // jax.random.key(1) -> key data (0, 1); split counters (hi=0, lo=t)
        tf2x32_host(0u, 1u, 0u, (unsigned)t, k0, k1);
        const unsigned k2 = k0 ^ k1 ^ 0x1BD11BDAu;
        sp.kA0[t] = k0;  sp.kB0[t] = k1;
        sp.kA1[t] = k1;  sp.kB1[t] = k2 + 1u;
        sp.kA2[t] = k2;  sp.kB2[t] = k0 + 2u;
        sp.kA3[t] = k0;  sp.kB3[t] = k1 + 3u;
        sp.kA4[t] = k1;  sp.kB4[t] = k2 + 4u;
        sp.kA5[t] = k2;  sp.kB5[t] = k0 + 5u;
        sp.inv[t] = 1.0f / (float)(TSTEPS - t);
    }

    const float* x  = (const float*)d_in[0];
    const float* mn = (const float*)d_in[1];
    const float* sd = (const float*)d_in[2];
    float* out = (float*)d_out;

    const int threads = 256;
    const int blocks = (NELEM / EPT + threads - 1) / threads;  // 9408 exactly
    hyper_kernel<<<blocks, threads>>>(x, mn, sd, out, sp);
}

// round 3
// speedup vs baseline: 1.3555x; 1.0308x over previous
#include <cuda_runtime.h>
#include <cstdint>

// Problem constants: x is [64,3,224,224] f32, out is [16,64,3,224,224] f32.
#define NELEM    9633792      // 64*3*224*224
#define HWPLANE  50176        // 224*224
#define TSTEPS   16
#define EPT      4            // elements per thread (float4 granularity)

// Host-precomputed per-step constants: threefry key schedule with round
// constants folded in, rn(1/slots), plus opaque integers that force ptxas
// to keep IMAD forms (it cannot constant-fold values from the param cbank).
struct StepParams {
    unsigned int kA0[TSTEPS], kB0[TSTEPS];             // initial inject (k0, k1)
    unsigned int kA1[TSTEPS], kB1[TSTEPS];             // (k1, k2+1)
    unsigned int kA2[TSTEPS], kB2[TSTEPS];             // (k2, k0+2)
    unsigned int kA3[TSTEPS], kB3[TSTEPS];             // (k0, k1+3)
    unsigned int kA4[TSTEPS], kB4[TSTEPS];             // (k1, k2+4)
    unsigned int kA5[TSTEPS], kB5[TSTEPS];             // (k2, k0+5)
    float        inv[TSTEPS];                          // rn(1/slots)
    unsigned int one;                                  // == 1  (opaque)
    unsigned int c23;                                  // == 1<<23 (opaque)
};

// Integer add forced onto the FMA pipe: IMAD Rd = Ra * one + Rb.
// 'one' comes from the constant bank, so ptxas can't strength-reduce it.
__device__ __forceinline__ unsigned addf(unsigned a, unsigned b, unsigned one) {
    unsigned d;
    asm("mad.lo.u32 %0, %1, %2, %3;" : "=r"(d) : "r"(a), "r"(one), "r"(b));
    return d;
}

// (bits >> 9) | 0x3f800000 as ONE fma-pipe op: hi32(bits * 2^23) + 0x3f800000
// (the OR operands are disjoint, so OR == ADD; bits>>9 <= 2^23-1, no carry).
__device__ __forceinline__ unsigned ubits(unsigned bits, unsigned c23) {
    unsigned d;
    asm("mad.hi.u32 %0, %1, %2, %3;" : "=r"(d) : "r"(bits), "r"(c23),
        "n"(0x3f800000));
    return d;
}

// ---------------------------------------------------------------------------
// threefry2x32 core, pre-folded key schedule (20 rounds, JAX-exact), with all
// adds on the FMA pipe and SHF/XOR on the ALU pipe.
// ---------------------------------------------------------------------------
__device__ __forceinline__ unsigned tf2x32_bits(
    unsigned a0, unsigned b0, unsigned a1, unsigned b1,
    unsigned a2, unsigned b2, unsigned a3, unsigned b3,
    unsigned a4, unsigned b4, unsigned a5, unsigned b5,
    unsigned c1, unsigned one)
{
    unsigned x0 = a0;                 // c0 = 0, so x0 = 0 + k0
    unsigned x1 = addf(c1, b0, one);
#define TFR(r) { x0 = addf(x1, x0, one); \
                 x1 = __funnelshift_l(x1, x1, (r)); x1 ^= x0; }
    TFR(13) TFR(15) TFR(26) TFR(6)
    x0 = addf(x0, a1, one); x1 = addf(x1, b1, one);
    TFR(17) TFR(29) TFR(16) TFR(24)
    x0 = addf(x0, a2, one); x1 = addf(x1, b2, one);
    TFR(13) TFR(15) TFR(26) TFR(6)
    x0 = addf(x0, a3, one); x1 = addf(x1, b3, one);
    TFR(17) TFR(29) TFR(16) TFR(24)
    x0 = addf(x0, a4, one); x1 = addf(x1, b4, one);
    TFR(13) TFR(15) TFR(26) TFR(6)
    x0 = addf(x0, a5, one); x1 = addf(x1, b5, one);
#undef TFR
    return x0 ^ x1;                   // partitionable fold: o0 ^ o1
}

// Correctly-rounded a/b for invariant b with c = rn(1/b) (Markstein).
__device__ __forceinline__ float div_rn_inv(float a, float b, float c) {
    float q0 = __fmul_rn(a, c);
    float r  = __fmaf_rn(-b, q0, a);
    return __fmaf_rn(r, c, q0);
}

static inline unsigned rotl_host(unsigned v, int r) {
    return (v << r) | (v >> (32 - r));
}

static void tf2x32_host(unsigned k0, unsigned k1,
                        unsigned c0, unsigned c1,
                        unsigned &o0, unsigned &o1) {
    unsigned k2 = k0 ^ k1 ^ 0x1BD11BDAu;
    unsigned x0 = c0 + k0;
    unsigned x1 = c1 + k1;
#define TFRH(r) { x0 += x1; x1 = rotl_host(x1, (r)); x1 ^= x0; }
    TFRH(13) TFRH(15) TFRH(26) TFRH(6)
    x0 += k1; x1 += k2 + 1u;
    TFRH(17) TFRH(29) TFRH(16) TFRH(24)
    x0 += k2; x1 += k0 + 2u;
    TFRH(13) TFRH(15) TFRH(26) TFRH(6)
    x0 += k0; x1 += k1 + 3u;
    TFRH(17) TFRH(29) TFRH(16) TFRH(24)
    x0 += k1; x1 += k2 + 4u;
    TFRH(13) TFRH(15) TFRH(26) TFRH(6)
    x0 += k2; x1 += k0 + 5u;
#undef TFRH
    o0 = x0; o1 = x1;
}

// ---------------------------------------------------------------------------
// Main kernel: each thread owns 4 consecutive elements (same channel) across
// all 16 time steps.
// ---------------------------------------------------------------------------
__global__ void __launch_bounds__(256)
hyper_kernel(const float* __restrict__ x,
             const float* __restrict__ meanv,
             const float* __restrict__ stdv,
             float* __restrict__ out,
             const StepParams sp)
{
    const unsigned tid = blockIdx.x * blockDim.x + threadIdx.x;
    const unsigned j = tid * EPT;
    if (j >= NELEM) return;

    const unsigned one = sp.one;
    const unsigned c23 = sp.c23;

    const unsigned c = (j / HWPLANE) % 3u;
    const float m = meanv[c];
    const float s = stdv[c];
    // Output values for spike=0 and spike=1: (spike - m) / s, IEEE divide.
    const float ov0 = __fdiv_rn(0.0f - m, s);
    const float ov1 = __fdiv_rn(1.0f - m, s);

    const float4 xv = *reinterpret_cast<const float4*>(x + j);

    // probs = clip(x*s + m, 0, 1) (separate rn mul + rn add, matching XLA);
    // rem0 = probs * 16 (exact).
    float rem[EPT];
    {
        const float xs[EPT] = {xv.x, xv.y, xv.z, xv.w};
#pragma unroll
        for (int e = 0; e < EPT; e++) {
            float pr = __fadd_rn(__fmul_rn(xs[e], s), m);
            pr = fminf(fmaxf(pr, 0.0f), 1.0f);
            rem[e] = __fmul_rn(pr, 16.0f);
        }
    }

#pragma unroll 1
    for (int t = 0; t < TSTEPS; t++) {
        const float slots   = (float)(TSTEPS - t);
        const float slotsm1 = slots - 1.0f;
        const float invs    = sp.inv[t];
        const unsigned a0 = sp.kA0[t], b0 = sp.kB0[t];
        const unsigned a1 = sp.kA1[t], b1 = sp.kB1[t];
        const unsigned a2 = sp.kA2[t], b2 = sp.kB2[t];
        const unsigned a3 = sp.kA3[t], b3 = sp.kB3[t];
        const unsigned a4 = sp.kA4[t], b4 = sp.kB4[t];
        const unsigned a5 = sp.kA5[t], b5 = sp.kB5[t];

        float ovals[EPT];
#pragma unroll
        for (int e = 0; e < EPT; e++) {
            const unsigned bits = tf2x32_bits(a0, b0, a1, b1, a2, b2,
                                              a3, b3, a4, b4, a5, b5,
                                              j + (unsigned)e, one);

            // u = bitcast((bits>>9) | 0x3f800000) - 1.0 (exact subtraction)
            const float u = __uint_as_float(ubits(bits, c23)) - 1.0f;

            // p = rn(rem/slots); reference's clip(p,0,1) is a provable no-op
            // because rem in [0, slots] is an invariant.
            const float p = div_rn_inv(rem[e], slots, invs);

            const bool spike = (u < p);
            const float spikef = spike ? 1.0f : 0.0f;
            // rem = clip(rem - spike, 0, slots-1) (all exact ops)
            rem[e] = fminf(fmaxf(rem[e] - spikef, 0.0f), slotsm1);
            ovals[e] = spike ? ov1 : ov0;
        }

        float4 o;
        o.x = ovals[0]; o.y = ovals[1]; o.z = ovals[2]; o.w = ovals[3];
        *reinterpret_cast<float4*>(out + (size_t)t * NELEM + j) = o;
    }
}

// ---------------------------------------------------------------------------
// Launch: compute per-step keys + folded schedule + reciprocals on the host
// (keys[t] = threefry((0,1),(0,t)) under the partitionable split).
// Pure CPU arithmetic + one kernel launch => graph-capturable, allocation-free.
// ---------------------------------------------------------------------------
extern "C" void kernel_launch(void* const* d_in, const int* in_sizes, int n_in,
                              void* d_out, int out_size) {
    (void)in_sizes; (void)n_in; (void)out_size;

    StepParams sp;
    for (int t = 0; t < TSTEPS; t++) {
        unsigned k0, k1;
        // jax.random.key(1) -> key data (0, 1); split counters (hi=0, lo=t)
        tf2x32_host(0u, 1u, 0u, (unsigned)t, k0, k1);
        const unsigned k2 = k0 ^ k1 ^ 0x1BD11BDAu;
        sp.kA0[t] = k0;  sp.kB0[t] = k1;
        sp.kA1[t] = k1;  sp.kB1[t] = k2 + 1u;
        sp.kA2[t] = k2;  sp.kB2[t] = k0 + 2u;
        sp.kA3[t] = k0;  sp.kB3[t] = k1 + 3u;
        sp.kA4[t] = k1;  sp.kB4[t] = k2 + 4u;
        sp.kA5[t] = k2;  sp.kB5[t] = k0 + 5u;
        sp.inv[t] = 1.0f / (float)(TSTEPS - t);
    }
    sp.one = 1u;
    sp.c23 = 1u << 23;

    const float* x  = (const float*)d_in[0];
    const float* mn = (const float*)d_in[1];
    const float* sd = (const float*)d_in[2];
    float* out = (float*)d_out;

    const int threads = 256;
    const int blocks = (NELEM / EPT + threads - 1) / threads;  // 9408 exactly
    hyper_kernel<<<blocks, threads>>>(x, mn, sd, out, sp);
}

// round 4
// speedup vs baseline: 1.3866x; 1.0229x over previous
#include <cuda_runtime.h>
#include <cstdint>

// Problem constants: x is [64,3,224,224] f32, out is [16,64,3,224,224] f32.
#define NELEM    9633792      // 64*3*224*224
#define HWPLANE  50176        // 224*224
#define TSTEPS   16
#define EPT      4            // elements per thread (float4 granularity)

// ---------------------------------------------------------------------------
// Compile-time key schedule: keys[t] = threefry2x32((0,1), (0,t)) under the
// partitionable split, with the 6 key-injection constants pre-folded.
// ---------------------------------------------------------------------------
struct Keys { unsigned a0,b0,a1,b1,a2,b2,a3,b3,a4,b4,a5,b5; };

__host__ __device__ constexpr unsigned rotlc(unsigned v, int r) {
    return (v << r) | (v >> (32 - r));
}

__host__ __device__ constexpr Keys make_keys(int t) {
    const unsigned k0 = 0u, k1 = 1u;
    const unsigned k2 = k0 ^ k1 ^ 0x1BD11BDAu;
    unsigned x0 = k0;                 // c0 = 0
    unsigned x1 = (unsigned)t + k1;   // c1 = t
    x0+=x1; x1=rotlc(x1,13); x1^=x0;
    x0+=x1; x1=rotlc(x1,15); x1^=x0;
    x0+=x1; x1=rotlc(x1,26); x1^=x0;
    x0+=x1; x1=rotlc(x1, 6); x1^=x0;
    x0+=k1; x1+=k2+1u;
    x0+=x1; x1=rotlc(x1,17); x1^=x0;
    x0+=x1; x1=rotlc(x1,29); x1^=x0;
    x0+=x1; x1=rotlc(x1,16); x1^=x0;
    x0+=x1; x1=rotlc(x1,24); x1^=x0;
    x0+=k2; x1+=k0+2u;
    x0+=x1; x1=rotlc(x1,13); x1^=x0;
    x0+=x1; x1=rotlc(x1,15); x1^=x0;
    x0+=x1; x1=rotlc(x1,26); x1^=x0;
    x0+=x1; x1=rotlc(x1, 6); x1^=x0;
    x0+=k0; x1+=k1+3u;
    x0+=x1; x1=rotlc(x1,17); x1^=x0;
    x0+=x1; x1=rotlc(x1,29); x1^=x0;
    x0+=x1; x1=rotlc(x1,16); x1^=x0;
    x0+=x1; x1=rotlc(x1,24); x1^=x0;
    x0+=k1; x1+=k2+4u;
    x0+=x1; x1=rotlc(x1,13); x1^=x0;
    x0+=x1; x1=rotlc(x1,15); x1^=x0;
    x0+=x1; x1=rotlc(x1,26); x1^=x0;
    x0+=x1; x1=rotlc(x1, 6); x1^=x0;
    x0+=k2; x1+=k0+5u;
    const unsigned K0 = x0, K1 = x1, K2 = K0 ^ K1 ^ 0x1BD11BDAu;
    return Keys{K0,K1, K1,K2+1u, K2,K0+2u, K0,K1+3u, K1,K2+4u, K2,K0+5u};
}

// ---------------------------------------------------------------------------
// FMA-pipe integer adds. 'one' (==1) comes from a kernel parameter, so ptxas
// cannot strength-reduce the IMAD forms back to IADD3.
// ---------------------------------------------------------------------------
__device__ __forceinline__ unsigned addf(unsigned a, unsigned b, unsigned one) {
    unsigned d;
    asm("mad.lo.u32 %0, %1, %2, %3;" : "=r"(d) : "r"(a), "r"(one), "r"(b));
    return d;
}

// x + IMM as IMAD with immediate multiplier: d = one * IMM + x.
template<unsigned IMM>
__device__ __forceinline__ unsigned addimm(unsigned x, unsigned one) {
    unsigned d;
    asm("mad.lo.u32 %0, %1, %2, %3;" : "=r"(d) : "r"(one), "n"(IMM), "r"(x));
    return d;
}

// (bits >> 9) | 0x3f800000 as one op: hi32(bits * 2^23) + 0x3f800000
// (disjoint bit ranges, so OR == ADD).
__device__ __forceinline__ unsigned ubits(unsigned bits, unsigned c23) {
    unsigned d;
    asm("mad.hi.u32 %0, %1, %2, %3;" : "=r"(d) : "r"(bits), "r"(c23),
        "n"(0x3f800000));
    return d;
}

// ---------------------------------------------------------------------------
// threefry2x32 (JAX-exact 20 rounds) with all key material as immediates.
// Returns o0 ^ o1 (partitionable bits fold).
// ---------------------------------------------------------------------------
template<unsigned A0,unsigned B0,unsigned A1,unsigned B1,unsigned A2,unsigned B2,
         unsigned A3,unsigned B3,unsigned A4,unsigned B4,unsigned A5,unsigned B5>
__device__ __forceinline__ unsigned tf_bits(unsigned c1, unsigned one) {
    unsigned x1 = addimm<B0>(c1, one);
    unsigned x0 = addimm<A0>(x1, one);   // round 1 add folded with x0 init
    x1 = __funnelshift_l(x1, x1, 13); x1 ^= x0;
#define TFR(r) { x0 = addf(x1, x0, one); \
                 x1 = __funnelshift_l(x1, x1, (r)); x1 ^= x0; }
    TFR(15) TFR(26) TFR(6)
    x0 = addimm<A1>(x0, one); x1 = addimm<B1>(x1, one);
    TFR(17) TFR(29) TFR(16) TFR(24)
    x0 = addimm<A2>(x0, one); x1 = addimm<B2>(x1, one);
    TFR(13) TFR(15) TFR(26) TFR(6)
    x0 = addimm<A3>(x0, one); x1 = addimm<B3>(x1, one);
    TFR(17) TFR(29) TFR(16) TFR(24)
    x0 = addimm<A4>(x0, one); x1 = addimm<B4>(x1, one);
    TFR(13) TFR(15) TFR(26) TFR(6)
    x0 = addimm<A5>(x0, one); x1 = addimm<B5>(x1, one);
#undef TFR
    return x0 ^ x1;
}

// ---------------------------------------------------------------------------
// One fully specialized time step for 4 elements.
// ---------------------------------------------------------------------------
template<int T>
__device__ __forceinline__ void do_step(float rem[EPT], unsigned j,
                                        float ov0, float ov1,
                                        unsigned one, unsigned c23,
                                        float* __restrict__ out)
{
    constexpr int   S    = TSTEPS - T;            // remaining slots
    constexpr float SF   = (float)S;
    constexpr float INV  = 1.0f / SF;             // rn(1/S), exact for pow2
    constexpr float SM1  = SF - 1.0f;
    constexpr bool  POW2 = (S & (S - 1)) == 0;
    constexpr Keys  K    = make_keys(T);

    float ovals[EPT];
#pragma unroll
    for (int e = 0; e < EPT; e++) {
        const unsigned bits =
            tf_bits<K.a0,K.b0,K.a1,K.b1,K.a2,K.b2,
                    K.a3,K.b3,K.a4,K.b4,K.a5,K.b5>(j + (unsigned)e, one);

        // u = bitcast((bits>>9)|0x3f800000) - 1.0 (exact Sterbenz subtraction)
        const float u = __uint_as_float(ubits(bits, c23)) - 1.0f;

        // p = rn(rem/S). The reference's clip(p,0,1) is a no-op since
        // rem in [0,S] is an invariant. pow2 S: single exact FMUL.
        float p;
        if (S == 1) {
            p = rem[e];
        } else if (POW2) {
            p = __fmul_rn(rem[e], INV);
        } else {
            const float q0 = __fmul_rn(rem[e], INV);
            const float r  = __fmaf_rn(-SF, q0, rem[e]);
            p = __fmaf_rn(r, INV, q0);            // Markstein, correctly rounded
        }

        const bool sp = (u < p);
        if (S > 1) {  // last step's rem is dead
            const float r2 = sp ? (rem[e] - 1.0f) : rem[e];
            rem[e] = fminf(fmaxf(r2, 0.0f), SM1);
        }
        ovals[e] = sp ? ov1 : ov0;
    }

    float4 o;
    o.x = ovals[0]; o.y = ovals[1]; o.z = ovals[2]; o.w = ovals[3];
    *reinterpret_cast<float4*>(out + (size_t)T * NELEM + j) = o;
}

// ---------------------------------------------------------------------------
// Main kernel: each thread owns 4 consecutive elements (same channel, since
// channel-plane boundaries are multiples of 4) across all 16 time steps.
// Grid covers NELEM exactly, so no bounds guard.
// ---------------------------------------------------------------------------
__global__ void __launch_bounds__(256)
hyper_kernel(const float* __restrict__ x,
             const float* __restrict__ meanv,
             const float* __restrict__ stdv,
             float* __restrict__ out,
             unsigned one, unsigned c23)
{
    const unsigned j = (blockIdx.x * blockDim.x + threadIdx.x) * EPT;

    const unsigned c = (j / HWPLANE) % 3u;
    const float m = meanv[c];
    const float s = stdv[c];
    // Output values for spike=0 and spike=1: (spike - m) / s, IEEE divide.
    const float ov0 = __fdiv_rn(0.0f - m, s);
    const float ov1 = __fdiv_rn(1.0f - m, s);

    const float4 xv = *reinterpret_cast<const float4*>(x + j);

    // probs = clip(x*s + m, 0, 1) (separate rn mul + rn add, matching XLA);
    // rem0 = probs * 16 (exact).
    float rem[EPT];
    {
        const float xs[EPT] = {xv.x, xv.y, xv.z, xv.w};
#pragma unroll
        for (int e = 0; e < EPT; e++) {
            float pr = __fadd_rn(__fmul_rn(xs[e], s), m);
            pr = fminf(fmaxf(pr, 0.0f), 1.0f);
            rem[e] = __fmul_rn(pr, 16.0f);
        }
    }

    do_step< 0>(rem, j, ov0, ov1, one, c23, out);
    do_step< 1>(rem, j, ov0, ov1, one, c23, out);
    do_step< 2>(rem, j, ov0, ov1, one, c23, out);
    do_step< 3>(rem, j, ov0, ov1, one, c23, out);
    do_step< 4>(rem, j, ov0, ov1, one, c23, out);
    do_step< 5>(rem, j, ov0, ov1, one, c23, out);
    do_step< 6>(rem, j, ov0, ov1, one, c23, out);
    do_step< 7>(rem, j, ov0, ov1, one, c23, out);
    do_step< 8>(rem, j, ov0, ov1, one, c23, out);
    do_step< 9>(rem, j, ov0, ov1, one, c23, out);
    do_step<10>(rem, j, ov0, ov1, one, c23, out);
    do_step<11>(rem, j, ov0, ov1, one, c23, out);
    do_step<12>(rem, j, ov0, ov1, one, c23, out);
    do_step<13>(rem, j, ov0, ov1, one, c23, out);
    do_step<14>(rem, j, ov0, ov1, one, c23, out);
    do_step<15>(rem, j, ov0, ov1, one, c23, out);
}

// ---------------------------------------------------------------------------
// Launch: single kernel, graph-capturable, allocation-free. The opaque
// 'one'/'c23' params keep the IMAD forms alive through ptxas.
// ---------------------------------------------------------------------------
extern "C" void kernel_launch(void* const* d_in, const int* in_sizes, int n_in,
                              void* d_out, int out_size) {
    (void)in_sizes; (void)n_in; (void)out_size;

    const float* x  = (const float*)d_in[0];
    const float* mn = (const float*)d_in[1];
    const float* sd = (const float*)d_in[2];
    float* out = (float*)d_out;

    const int threads = 256;
    const int blocks = NELEM / (threads * EPT);   // 9408 exactly
    hyper_kernel<<<blocks, threads>>>(x, mn, sd, out, 1u, 1u << 23);
}